// round 15
// baseline (speedup 1.0000x reference)
#include <cuda_runtime.h>
#include <cuda_fp16.h>
#include <mma.h>

using namespace nvcuda;

// ---------------- problem constants ----------------
#define DMODEL 1024
#define NHEADS 16
#define DK     64
#define DFF    4096
#define BATCH  2
#define SEQ    2048
#define NTOK   (BATCH*SEQ)          // 4096
#define LN_EPS 1e-3f

// ---------------- scratch (device globals; no allocation allowed) -------------
__device__ __half g_xb   [NTOK*DMODEL];
__device__ __half g_Wqb  [DMODEL*DMODEL];
__device__ __half g_Wkb  [DMODEL*DMODEL];
__device__ __half g_Wvb  [DMODEL*DMODEL];
__device__ __half g_Wob  [DMODEL*DMODEL];
__device__ __half g_W1b  [DMODEL*DFF];
__device__ __half g_W2b  [DFF*DMODEL];
__device__ __half g_Q    [NTOK*DMODEL];   // [B,H,S,DK]
__device__ __half g_K    [NTOK*DMODEL];   // [B,H,S,DK]
__device__ __half g_V    [NTOK*DMODEL];   // [B,H,S,DK]
__device__ __half g_att  [NTOK*DMODEL];   // [tok, DMODEL]
__device__ float  g_oproj[NTOK*DMODEL];
__device__ float  g_h    [NTOK*DMODEL];
__device__ __half g_hb   [NTOK*DMODEL];
__device__ __half g_y1   [NTOK*DFF];
__device__ float  g_ffn2 [NTOK*DMODEL];
__device__ float  g_logw [NTOK];

// ---------------- tiny elementwise kernels ----------------
__global__ void f2h_kernel(const float* __restrict__ a, __half* __restrict__ o, int n) {
    int i = blockIdx.x * blockDim.x + threadIdx.x;
    if (i < n) o[i] = __float2half(a[i]);
}

__global__ void logw_kernel(const float* __restrict__ w, float* __restrict__ o, int n) {
    int i = blockIdx.x * blockDim.x + threadIdx.x;
    if (i < n) o[i] = logf(w[i] + 1e-20f);
}

// ---------------- generic fp16 GEMM with fused epilogue ----------------
// C = A(MxK) @ B(KxN) + bias, fp32 accumulate.
// EPI: 0 -> fp32 row-major; 1 -> fp16 row-major; 2 -> relu + fp16 row-major;
//      3 -> fp16 scattered to [B,H,S,DK] layout (QKV)
#define BM 128
#define BN 128
#define BKK 32

template<int EPI>
__global__ void __launch_bounds__(256) gemm_f16(
    const __half* __restrict__ A, const __half* __restrict__ B,
    const float* __restrict__ bias, void* __restrict__ C,
    int M, int N, int K)
{
    __shared__ __half As[BM][BKK + 8];   // ld 40 (80B, mult of 16B)
    __shared__ __half Bs[BKK][BN + 8];   // ld 136 (272B)
    __shared__ float  epi[8][256];

    const int tid  = threadIdx.x;
    const int bm   = blockIdx.y, bn = blockIdx.x;
    const int warp = tid >> 5, lane = tid & 31;
    const int wr   = warp >> 2, wc = warp & 3;   // 2x4 warp grid; warp tile 64x32

    wmma::fragment<wmma::accumulator, 16, 16, 16, float> c[4][2];
#pragma unroll
    for (int i = 0; i < 4; i++)
#pragma unroll
        for (int j = 0; j < 2; j++) wmma::fill_fragment(c[i][j], 0.0f);

    const __half* Ab = A + (size_t)bm * BM * K;
    const __half* Bb = B + (size_t)bn * BN;

    const int arow = tid >> 2, acol = (tid & 3) * 8;
    const int brow = tid >> 4, bcol = (tid & 15) * 8;

    for (int k0 = 0; k0 < K; k0 += BKK) {
#pragma unroll
        for (int i = 0; i < 2; i++) {
            int r = arow + i * 64;
            *(int4*)&As[r][acol] = *(const int4*)&Ab[(size_t)r * K + k0 + acol];
        }
#pragma unroll
        for (int i = 0; i < 2; i++) {
            int r = brow + i * 16;
            *(int4*)&Bs[r][bcol] = *(const int4*)&Bb[(size_t)(k0 + r) * N + bcol];
        }
        __syncthreads();

#pragma unroll
        for (int kk = 0; kk < BKK; kk += 16) {
            wmma::fragment<wmma::matrix_a, 16, 16, 16, __half, wmma::row_major> a[4];
            wmma::fragment<wmma::matrix_b, 16, 16, 16, __half, wmma::row_major> b[2];
#pragma unroll
            for (int i = 0; i < 4; i++)
                wmma::load_matrix_sync(a[i], &As[wr * 64 + i * 16][kk], BKK + 8);
#pragma unroll
            for (int j = 0; j < 2; j++)
                wmma::load_matrix_sync(b[j], &Bs[kk][wc * 32 + j * 16], BN + 8);
#pragma unroll
            for (int i = 0; i < 4; i++)
#pragma unroll
                for (int j = 0; j < 2; j++)
                    wmma::mma_sync(c[i][j], a[i], b[j], c[i][j]);
        }
        __syncthreads();
    }

    // epilogue: stage each 16x16 frag through smem, apply bias + EPI, store
#pragma unroll
    for (int i = 0; i < 4; i++) {
#pragma unroll
        for (int j = 0; j < 2; j++) {
            wmma::store_matrix_sync(epi[warp], c[i][j], 16, wmma::mem_row_major);
            __syncwarp();
            const int gr0 = bm * BM + wr * 64 + i * 16;
            const int gc0 = bn * BN + wc * 32 + j * 16;
#pragma unroll
            for (int e = 0; e < 8; e++) {
                int idx = lane * 8 + e;
                int r = idx >> 4, cc = idx & 15;
                int grow = gr0 + r, gcol = gc0 + cc;
                float v = epi[warp][idx] + bias[gcol];
                if (EPI == 0) {
                    ((float*)C)[(size_t)grow * N + gcol] = v;
                } else if (EPI == 1) {
                    ((__half*)C)[(size_t)grow * N + gcol] = __float2half(v);
                } else if (EPI == 2) {
                    ((__half*)C)[(size_t)grow * N + gcol] = __float2half(fmaxf(v, 0.0f));
                } else { // QKV scatter: grow = token, gcol = channel
                    int b_ = grow >> 11, s_ = grow & 2047;
                    int h_ = gcol >> 6,  d_ = gcol & 63;
                    ((__half*)C)[((((size_t)b_ * NHEADS + h_) * SEQ + s_) << 6) + d_] =
                        __float2half(v);
                }
            }
            __syncwarp();
        }
    }
}

// ---------------- flash attention ----------------
// grid: (SEQ/64, BATCH*NHEADS), 128 threads (4 warps). Br=Bc=64, D=64.
// Q pre-scaled by 1/sqrt(DK). Scores get per-key log-weight bias.
#define FLASH_SMEM (4*64*72*2 /*Qs,Ks,Vs,Ps*/ + 2*64*68*4 /*Ss,Os*/ + 4*64*4)

__global__ void __launch_bounds__(128) flash_attn(
    const __half* __restrict__ Q, const __half* __restrict__ K,
    const __half* __restrict__ V, const float* __restrict__ logw,
    __half* __restrict__ attout)
{
    extern __shared__ char smem[];
    __half* Qs = (__half*)smem;           // 64 x 72
    __half* Ks = Qs + 64 * 72;
    __half* Vs = Ks + 64 * 72;
    __half* Ps = Vs + 64 * 72;
    float*  Ss = (float*)(Ps + 64 * 72);  // 64 x 68
    float*  Os = Ss + 64 * 68;            // 64 x 68
    float*  lw   = Os + 64 * 68;          // 64
    float*  mrow = lw + 64;
    float*  lrow = mrow + 64;
    float*  arow = lrow + 64;

    const int tid = threadIdx.x;
    const int warp = tid >> 5;
    const int qb = blockIdx.x * 64;
    const int bh = blockIdx.y;            // b*16 + h
    const int b  = bh >> 4;
    const int h  = bh & 15;

    const __half* Qbase = Q + ((size_t)bh * SEQ + qb) * DK;
    const __half* Kb    = K + (size_t)bh * SEQ * DK;
    const __half* Vb    = V + (size_t)bh * SEQ * DK;
    const float*  lwb   = logw + b * SEQ;

    // load Q tile, scaled by 1/8
    for (int i = tid; i < 64 * 8; i += 128) {
        int r = i >> 3, c8 = (i & 7) * 8;
        int4 v4 = *(const int4*)&Qbase[r * DK + c8];
        __half* hv = (__half*)&v4;
#pragma unroll
        for (int e = 0; e < 8; e++) hv[e] = __float2half(__half2float(hv[e]) * 0.125f);
        *(int4*)&Qs[r * 72 + c8] = v4;
    }
    for (int i = tid; i < 64 * 68; i += 128) Os[i] = 0.0f;
    if (tid < 64) { mrow[tid] = -1e30f; lrow[tid] = 0.0f; }
    __syncthreads();

    for (int kt = 0; kt < SEQ; kt += 64) {
        // load K/V tiles + log-weight slice
        for (int i = tid; i < 512; i += 128) {
            int r = i >> 3, c8 = (i & 7) * 8;
            *(int4*)&Ks[r * 72 + c8] = *(const int4*)&Kb[(size_t)(kt + r) * DK + c8];
            *(int4*)&Vs[r * 72 + c8] = *(const int4*)&Vb[(size_t)(kt + r) * DK + c8];
        }
        if (tid < 64) lw[tid] = lwb[kt + tid];
        __syncthreads();

        // S = Q @ K^T  (warp owns 16 rows)
        {
            wmma::fragment<wmma::accumulator, 16, 16, 16, float> s[4];
#pragma unroll
            for (int n = 0; n < 4; n++) wmma::fill_fragment(s[n], 0.0f);
#pragma unroll
            for (int k = 0; k < 4; k++) {
                wmma::fragment<wmma::matrix_a, 16, 16, 16, __half, wmma::row_major> a;
                wmma::load_matrix_sync(a, &Qs[(warp * 16) * 72 + k * 16], 72);
#pragma unroll
                for (int n = 0; n < 4; n++) {
                    wmma::fragment<wmma::matrix_b, 16, 16, 16, __half, wmma::col_major> bb;
                    wmma::load_matrix_sync(bb, &Ks[(n * 16) * 72 + k * 16], 72);
                    wmma::mma_sync(s[n], a, bb, s[n]);
                }
            }
#pragma unroll
            for (int n = 0; n < 4; n++)
                wmma::store_matrix_sync(&Ss[(warp * 16) * 68 + n * 16], s[n], 68,
                                        wmma::mem_row_major);
        }
        __syncthreads();

        // online softmax: 2 threads per row
        {
            int r = tid >> 1, j = tid & 1;
            float* Sr = &Ss[r * 68 + j * 32];
            const float* lwp = &lw[j * 32];
            float mx = -1e30f;
#pragma unroll
            for (int cc = 0; cc < 32; cc++) {
                float v = Sr[cc] + lwp[cc];
                Sr[cc] = v;
                mx = fmaxf(mx, v);
            }
            mx = fmaxf(mx, __shfl_xor_sync(0xffffffffu, mx, 1));
            float mold = mrow[r];
            float mnew = fmaxf(mold, mx);
            float sum = 0.0f;
            __half* Pr = &Ps[r * 72 + j * 32];
#pragma unroll
            for (int cc = 0; cc < 32; cc++) {
                float p = __expf(Sr[cc] - mnew);
                sum += p;
                Pr[cc] = __float2half(p);
            }
            sum += __shfl_xor_sync(0xffffffffu, sum, 1);
            if (j == 0) {
                float a = __expf(mold - mnew);
                mrow[r] = mnew;
                lrow[r] = lrow[r] * a + sum;
                arow[r] = a;
            }
        }
        __syncthreads();

        // PV = P @ V  -> staged into Ss
        {
            wmma::fragment<wmma::accumulator, 16, 16, 16, float> pv[4];
#pragma unroll
            for (int n = 0; n < 4; n++) wmma::fill_fragment(pv[n], 0.0f);
#pragma unroll
            for (int k = 0; k < 4; k++) {
                wmma::fragment<wmma::matrix_a, 16, 16, 16, __half, wmma::row_major> a;
                wmma::load_matrix_sync(a, &Ps[(warp * 16) * 72 + k * 16], 72);
#pragma unroll
                for (int n = 0; n < 4; n++) {
                    wmma::fragment<wmma::matrix_b, 16, 16, 16, __half, wmma::row_major> bb;
                    wmma::load_matrix_sync(bb, &Vs[(k * 16) * 72 + n * 16], 72);
                    wmma::mma_sync(pv[n], a, bb, pv[n]);
                }
            }
#pragma unroll
            for (int n = 0; n < 4; n++)
                wmma::store_matrix_sync(&Ss[(warp * 16) * 68 + n * 16], pv[n], 68,
                                        wmma::mem_row_major);
        }
        __syncthreads();

        // O = O * alpha + PV
        for (int i = tid; i < 4096; i += 128) {
            int r = i >> 6, cc = i & 63;
            Os[r * 68 + cc] = Os[r * 68 + cc] * arow[r] + Ss[r * 68 + cc];
        }
        __syncthreads();
    }

    // write O / l  to [tok, DMODEL] fp16
    for (int i = tid; i < 4096; i += 128) {
        int r = i >> 6, cc = i & 63;
        float v = Os[r * 68 + cc] / lrow[r];
        attout[(size_t)(b * SEQ + qb + r) * DMODEL + h * DK + cc] = __float2half(v);
    }
}

// ---------------- fused residual + LayerNorm ----------------
__device__ __forceinline__ float block_sum256(float v, float* red) {
#pragma unroll
    for (int o = 16; o; o >>= 1) v += __shfl_xor_sync(0xffffffffu, v, o);
    int tid = threadIdx.x;
    if ((tid & 31) == 0) red[tid >> 5] = v;
    __syncthreads();
    float s = 0.0f;
#pragma unroll
    for (int w = 0; w < 8; w++) s += red[w];
    __syncthreads();
    return s;
}

__global__ void __launch_bounds__(256) ln_kernel(
    const float* __restrict__ a, const float* __restrict__ b,
    const float* __restrict__ g, const float* __restrict__ be,
    float* __restrict__ out, __half* __restrict__ outh)
{
    __shared__ float red[8];
    const int row = blockIdx.x, tid = threadIdx.x;
    const size_t base = (size_t)row * DMODEL;
    float v[4];
    float s = 0.0f;
#pragma unroll
    for (int i = 0; i < 4; i++) {
        int c = tid + 256 * i;
        v[i] = a[base + c] + b[base + c];
        s += v[i];
    }
    float mu = block_sum256(s, red) * (1.0f / DMODEL);
    float q = 0.0f;
#pragma unroll
    for (int i = 0; i < 4; i++) { float d = v[i] - mu; q += d * d; }
    float var = block_sum256(q, red) * (1.0f / DMODEL);
    float rstd = rsqrtf(var + LN_EPS);
#pragma unroll
    for (int i = 0; i < 4; i++) {
        int c = tid + 256 * i;
        float o = (v[i] - mu) * rstd * g[c] + be[c];
        out[base + c] = o;
        if (outh) outh[base + c] = __float2half(o);
    }
}

// ---------------- host launcher ----------------
static void* sym(const void* s) { void* p = nullptr; cudaGetSymbolAddress(&p, s); return p; }

extern "C" void kernel_launch(void* const* d_in, const int* in_sizes, int n_in,
                              void* d_out, int out_size)
{
    const float* x   = (const float*)d_in[0];
    const float* wts = (const float*)d_in[1];
    const float* Wq  = (const float*)d_in[2];
    const float* bq  = (const float*)d_in[3];
    const float* Wk  = (const float*)d_in[4];
    const float* bk  = (const float*)d_in[5];
    const float* Wv  = (const float*)d_in[6];
    const float* bv  = (const float*)d_in[7];
    const float* Wo  = (const float*)d_in[8];
    const float* bo  = (const float*)d_in[9];
    const float* W1  = (const float*)d_in[10];
    const float* b1  = (const float*)d_in[11];
    const float* W2  = (const float*)d_in[12];
    const float* b2  = (const float*)d_in[13];
    const float* g1  = (const float*)d_in[14];
    const float* be1 = (const float*)d_in[15];
    const float* g2  = (const float*)d_in[16];
    const float* be2 = (const float*)d_in[17];

    __half* xb   = (__half*)sym(g_xb);
    __half* Wqb  = (__half*)sym(g_Wqb);
    __half* Wkb  = (__half*)sym(g_Wkb);
    __half* Wvb  = (__half*)sym(g_Wvb);
    __half* Wob  = (__half*)sym(g_Wob);
    __half* W1b  = (__half*)sym(g_W1b);
    __half* W2b  = (__half*)sym(g_W2b);
    __half* Qd   = (__half*)sym(g_Q);
    __half* Kd   = (__half*)sym(g_K);
    __half* Vd   = (__half*)sym(g_V);
    __half* attb = (__half*)sym(g_att);
    float*  oproj= (float*)sym(g_oproj);
    float*  hbuf = (float*)sym(g_h);
    __half* hb   = (__half*)sym(g_hb);
    __half* y1   = (__half*)sym(g_y1);
    float*  ffn2 = (float*)sym(g_ffn2);
    float*  logw = (float*)sym(g_logw);

    cudaFuncSetAttribute((const void*)flash_attn,
                         cudaFuncAttributeMaxDynamicSharedMemorySize, FLASH_SMEM);

    const int T = 256;
    // fp32 -> fp16 conversions
    f2h_kernel<<<(NTOK*DMODEL + T-1)/T, T>>>(x,  xb,  NTOK*DMODEL);
    f2h_kernel<<<(DMODEL*DMODEL + T-1)/T, T>>>(Wq, Wqb, DMODEL*DMODEL);
    f2h_kernel<<<(DMODEL*DMODEL + T-1)/T, T>>>(Wk, Wkb, DMODEL*DMODEL);
    f2h_kernel<<<(DMODEL*DMODEL + T-1)/T, T>>>(Wv, Wvb, DMODEL*DMODEL);
    f2h_kernel<<<(DMODEL*DMODEL + T-1)/T, T>>>(Wo, Wob, DMODEL*DMODEL);
    f2h_kernel<<<(DMODEL*DFF + T-1)/T, T>>>(W1, W1b, DMODEL*DFF);
    f2h_kernel<<<(DFF*DMODEL + T-1)/T, T>>>(W2, W2b, DFF*DMODEL);
    logw_kernel<<<(NTOK + T-1)/T, T>>>(wts, logw, NTOK);

    // Q, K, V projections (scattered to [B,H,S,DK])
    dim3 gQKV(DMODEL/BN, NTOK/BM);
    gemm_f16<3><<<gQKV, 256>>>(xb, Wqb, bq, Qd, NTOK, DMODEL, DMODEL);
    gemm_f16<3><<<gQKV, 256>>>(xb, Wkb, bk, Kd, NTOK, DMODEL, DMODEL);
    gemm_f16<3><<<gQKV, 256>>>(xb, Wvb, bv, Vd, NTOK, DMODEL, DMODEL);

    // attention
    flash_attn<<<dim3(SEQ/64, BATCH*NHEADS), 128, FLASH_SMEM>>>(Qd, Kd, Vd, logw, attb);

    // output projection (fp32)
    gemm_f16<0><<<dim3(DMODEL/BN, NTOK/BM), 256>>>(attb, Wob, bo, oproj,
                                                   NTOK, DMODEL, DMODEL);
    // h = LN(x + attn_out), also fp16 copy
    ln_kernel<<<NTOK, 256>>>(x, oproj, g1, be1, hbuf, hb);

    // FFN
    gemm_f16<2><<<dim3(DFF/BN, NTOK/BM), 256>>>(hb, W1b, b1, y1, NTOK, DFF, DMODEL);
    gemm_f16<0><<<dim3(DMODEL/BN, NTOK/BM), 256>>>(y1, W2b, b2, ffn2, NTOK, DMODEL, DFF);

    // out = LN(h + ffn)
    ln_kernel<<<NTOK, 256>>>(hbuf, ffn2, g2, be2, (float*)d_out, nullptr);
}

// round 16
// speedup vs baseline: 1.0077x; 1.0077x over previous
#include <cuda_runtime.h>
#include <cuda_fp16.h>
#include <mma.h>

using namespace nvcuda;

// ---------------- problem constants ----------------
#define DMODEL 1024
#define NHEADS 16
#define DK     64
#define DFF    4096
#define BATCH  2
#define SEQ    2048
#define NTOK   (BATCH*SEQ)          // 4096
#define LN_EPS 1e-3f

// ---------------- scratch (device globals; no allocation allowed) -------------
__device__ __half g_xb   [NTOK*DMODEL];
__device__ __half g_Wqb  [DMODEL*DMODEL];
__device__ __half g_Wkb  [DMODEL*DMODEL];
__device__ __half g_Wvb  [DMODEL*DMODEL];
__device__ __half g_Wob  [DMODEL*DMODEL];
__device__ __half g_W1b  [DMODEL*DFF];
__device__ __half g_W2b  [DFF*DMODEL];
__device__ __half g_Q    [NTOK*DMODEL];   // [B,H,S,DK]
__device__ __half g_K    [NTOK*DMODEL];   // [B,H,S,DK]
__device__ __half g_V    [NTOK*DMODEL];   // [B,H,S,DK]
__device__ __half g_att  [NTOK*DMODEL];   // [tok, DMODEL]
__device__ float  g_oproj[NTOK*DMODEL];
__device__ float  g_h    [NTOK*DMODEL];
__device__ __half g_hb   [NTOK*DMODEL];
__device__ __half g_y1   [NTOK*DFF];
__device__ float  g_ffn2 [NTOK*DMODEL];
__device__ float  g_logw [NTOK];

// ---------------- tiny elementwise kernels ----------------
__global__ void f2h_kernel(const float* __restrict__ a, __half* __restrict__ o, int n) {
    int i = blockIdx.x * blockDim.x + threadIdx.x;
    if (i < n) o[i] = __float2half(a[i]);
}

__global__ void logw_kernel(const float* __restrict__ w, float* __restrict__ o, int n) {
    int i = blockIdx.x * blockDim.x + threadIdx.x;
    if (i < n) o[i] = logf(w[i] + 1e-20f);
}

// ---------------- generic fp16 GEMM with fused epilogue ----------------
// C = A(MxK) @ B(KxN) + bias, fp32 accumulate.
// EPI: 0 -> fp32 row-major; 1 -> fp16 row-major; 2 -> relu + fp16 row-major;
//      3 -> fp16 scattered to [B,H,S,DK] layout (QKV)
#define BM 128
#define BN 128
#define BKK 32

template<int EPI>
__global__ void __launch_bounds__(256) gemm_f16(
    const __half* __restrict__ A, const __half* __restrict__ B,
    const float* __restrict__ bias, void* __restrict__ C,
    int M, int N, int K)
{
    __shared__ __half As[BM][BKK + 8];   // ld 40 (80B, mult of 16B)
    __shared__ __half Bs[BKK][BN + 8];   // ld 136 (272B)
    __shared__ float  epi[8][256];

    const int tid  = threadIdx.x;
    const int bm   = blockIdx.y, bn = blockIdx.x;
    const int warp = tid >> 5, lane = tid & 31;
    const int wr   = warp >> 2, wc = warp & 3;   // 2x4 warp grid; warp tile 64x32

    wmma::fragment<wmma::accumulator, 16, 16, 16, float> c[4][2];
#pragma unroll
    for (int i = 0; i < 4; i++)
#pragma unroll
        for (int j = 0; j < 2; j++) wmma::fill_fragment(c[i][j], 0.0f);

    const __half* Ab = A + (size_t)bm * BM * K;
    const __half* Bb = B + (size_t)bn * BN;

    const int arow = tid >> 2, acol = (tid & 3) * 8;
    const int brow = tid >> 4, bcol = (tid & 15) * 8;

    for (int k0 = 0; k0 < K; k0 += BKK) {
#pragma unroll
        for (int i = 0; i < 2; i++) {
            int r = arow + i * 64;
            *(int4*)&As[r][acol] = *(const int4*)&Ab[(size_t)r * K + k0 + acol];
        }
#pragma unroll
        for (int i = 0; i < 2; i++) {
            int r = brow + i * 16;
            *(int4*)&Bs[r][bcol] = *(const int4*)&Bb[(size_t)(k0 + r) * N + bcol];
        }
        __syncthreads();

#pragma unroll
        for (int kk = 0; kk < BKK; kk += 16) {
            wmma::fragment<wmma::matrix_a, 16, 16, 16, __half, wmma::row_major> a[4];
            wmma::fragment<wmma::matrix_b, 16, 16, 16, __half, wmma::row_major> b[2];
#pragma unroll
            for (int i = 0; i < 4; i++)
                wmma::load_matrix_sync(a[i], &As[wr * 64 + i * 16][kk], BKK + 8);
#pragma unroll
            for (int j = 0; j < 2; j++)
                wmma::load_matrix_sync(b[j], &Bs[kk][wc * 32 + j * 16], BN + 8);
#pragma unroll
            for (int i = 0; i < 4; i++)
#pragma unroll
                for (int j = 0; j < 2; j++)
                    wmma::mma_sync(c[i][j], a[i], b[j], c[i][j]);
        }
        __syncthreads();
    }

    // epilogue: stage each 16x16 frag through smem, apply bias + EPI, store
#pragma unroll
    for (int i = 0; i < 4; i++) {
#pragma unroll
        for (int j = 0; j < 2; j++) {
            wmma::store_matrix_sync(epi[warp], c[i][j], 16, wmma::mem_row_major);
            __syncwarp();
            const int gr0 = bm * BM + wr * 64 + i * 16;
            const int gc0 = bn * BN + wc * 32 + j * 16;
#pragma unroll
            for (int e = 0; e < 8; e++) {
                int idx = lane * 8 + e;
                int r = idx >> 4, cc = idx & 15;
                int grow = gr0 + r, gcol = gc0 + cc;
                float v = epi[warp][idx] + bias[gcol];
                if (EPI == 0) {
                    ((float*)C)[(size_t)grow * N + gcol] = v;
                } else if (EPI == 1) {
                    ((__half*)C)[(size_t)grow * N + gcol] = __float2half(v);
                } else if (EPI == 2) {
                    ((__half*)C)[(size_t)grow * N + gcol] = __float2half(fmaxf(v, 0.0f));
                } else { // QKV scatter: grow = token, gcol = channel
                    int b_ = grow >> 11, s_ = grow & 2047;
                    int h_ = gcol >> 6,  d_ = gcol & 63;
                    ((__half*)C)[((((size_t)b_ * NHEADS + h_) * SEQ + s_) << 6) + d_] =
                        __float2half(v);
                }
            }
            __syncwarp();
        }
    }
}

// ---------------- flash attention ----------------
// grid: (SEQ/64, BATCH*NHEADS), 128 threads (4 warps). Br=Bc=64, D=64.
// Q pre-scaled by 1/sqrt(DK). Scores get per-key log-weight bias.
#define FLASH_SMEM (4*64*72*2 /*Qs,Ks,Vs,Ps*/ + 2*64*68*4 /*Ss,Os*/ + 4*64*4)

__global__ void __launch_bounds__(128) flash_attn(
    const __half* __restrict__ Q, const __half* __restrict__ K,
    const __half* __restrict__ V, const float* __restrict__ logw,
    __half* __restrict__ attout)
{
    extern __shared__ char smem[];
    __half* Qs = (__half*)smem;           // 64 x 72
    __half* Ks = Qs + 64 * 72;
    __half* Vs = Ks + 64 * 72;
    __half* Ps = Vs + 64 * 72;
    float*  Ss = (float*)(Ps + 64 * 72);  // 64 x 68
    float*  Os = Ss + 64 * 68;            // 64 x 68
    float*  lw   = Os + 64 * 68;          // 64
    float*  mrow = lw + 64;
    float*  lrow = mrow + 64;
    float*  arow = lrow + 64;

    const int tid = threadIdx.x;
    const int warp = tid >> 5;
    const int qb = blockIdx.x * 64;
    const int bh = blockIdx.y;            // b*16 + h
    const int b  = bh >> 4;
    const int h  = bh & 15;

    const __half* Qbase = Q + ((size_t)bh * SEQ + qb) * DK;
    const __half* Kb    = K + (size_t)bh * SEQ * DK;
    const __half* Vb    = V + (size_t)bh * SEQ * DK;
    const float*  lwb   = logw + b * SEQ;

    // load Q tile, scaled by 1/8
    for (int i = tid; i < 64 * 8; i += 128) {
        int r = i >> 3, c8 = (i & 7) * 8;
        int4 v4 = *(const int4*)&Qbase[r * DK + c8];
        __half* hv = (__half*)&v4;
#pragma unroll
        for (int e = 0; e < 8; e++) hv[e] = __float2half(__half2float(hv[e]) * 0.125f);
        *(int4*)&Qs[r * 72 + c8] = v4;
    }
    for (int i = tid; i < 64 * 68; i += 128) Os[i] = 0.0f;
    if (tid < 64) { mrow[tid] = -1e30f; lrow[tid] = 0.0f; }
    __syncthreads();

    for (int kt = 0; kt < SEQ; kt += 64) {
        // load K/V tiles + log-weight slice
        for (int i = tid; i < 512; i += 128) {
            int r = i >> 3, c8 = (i & 7) * 8;
            *(int4*)&Ks[r * 72 + c8] = *(const int4*)&Kb[(size_t)(kt + r) * DK + c8];
            *(int4*)&Vs[r * 72 + c8] = *(const int4*)&Vb[(size_t)(kt + r) * DK + c8];
        }
        if (tid < 64) lw[tid] = lwb[kt + tid];
        __syncthreads();

        // S = Q @ K^T  (warp owns 16 rows)
        {
            wmma::fragment<wmma::accumulator, 16, 16, 16, float> s[4];
#pragma unroll
            for (int n = 0; n < 4; n++) wmma::fill_fragment(s[n], 0.0f);
#pragma unroll
            for (int k = 0; k < 4; k++) {
                wmma::fragment<wmma::matrix_a, 16, 16, 16, __half, wmma::row_major> a;
                wmma::load_matrix_sync(a, &Qs[(warp * 16) * 72 + k * 16], 72);
#pragma unroll
                for (int n = 0; n < 4; n++) {
                    wmma::fragment<wmma::matrix_b, 16, 16, 16, __half, wmma::col_major> bb;
                    wmma::load_matrix_sync(bb, &Ks[(n * 16) * 72 + k * 16], 72);
                    wmma::mma_sync(s[n], a, bb, s[n]);
                }
            }
#pragma unroll
            for (int n = 0; n < 4; n++)
                wmma::store_matrix_sync(&Ss[(warp * 16) * 68 + n * 16], s[n], 68,
                                        wmma::mem_row_major);
        }
        __syncthreads();

        // online softmax: 2 threads per row
        {
            int r = tid >> 1, j = tid & 1;
            float* Sr = &Ss[r * 68 + j * 32];
            const float* lwp = &lw[j * 32];
            float mx = -1e30f;
#pragma unroll
            for (int cc = 0; cc < 32; cc++) {
                float v = Sr[cc] + lwp[cc];
                Sr[cc] = v;
                mx = fmaxf(mx, v);
            }
            mx = fmaxf(mx, __shfl_xor_sync(0xffffffffu, mx, 1));
            float mold = mrow[r];
            float mnew = fmaxf(mold, mx);
            float sum = 0.0f;
            __half* Pr = &Ps[r * 72 + j * 32];
#pragma unroll
            for (int cc = 0; cc < 32; cc++) {
                float p = __expf(Sr[cc] - mnew);
                sum += p;
                Pr[cc] = __float2half(p);
            }
            sum += __shfl_xor_sync(0xffffffffu, sum, 1);
            if (j == 0) {
                float a = __expf(mold - mnew);
                mrow[r] = mnew;
                lrow[r] = lrow[r] * a + sum;
                arow[r] = a;
            }
        }
        __syncthreads();

        // PV = P @ V  -> staged into Ss
        {
            wmma::fragment<wmma::accumulator, 16, 16, 16, float> pv[4];
#pragma unroll
            for (int n = 0; n < 4; n++) wmma::fill_fragment(pv[n], 0.0f);
#pragma unroll
            for (int k = 0; k < 4; k++) {
                wmma::fragment<wmma::matrix_a, 16, 16, 16, __half, wmma::row_major> a;
                wmma::load_matrix_sync(a, &Ps[(warp * 16) * 72 + k * 16], 72);
#pragma unroll
                for (int n = 0; n < 4; n++) {
                    wmma::fragment<wmma::matrix_b, 16, 16, 16, __half, wmma::row_major> bb;
                    wmma::load_matrix_sync(bb, &Vs[(k * 16) * 72 + n * 16], 72);
                    wmma::mma_sync(pv[n], a, bb, pv[n]);
                }
            }
#pragma unroll
            for (int n = 0; n < 4; n++)
                wmma::store_matrix_sync(&Ss[(warp * 16) * 68 + n * 16], pv[n], 68,
                                        wmma::mem_row_major);
        }
        __syncthreads();

        // O = O * alpha + PV
        for (int i = tid; i < 4096; i += 128) {
            int r = i >> 6, cc = i & 63;
            Os[r * 68 + cc] = Os[r * 68 + cc] * arow[r] + Ss[r * 68 + cc];
        }
        __syncthreads();
    }

    // write O / l  to [tok, DMODEL] fp16
    for (int i = tid; i < 4096; i += 128) {
        int r = i >> 6, cc = i & 63;
        float v = Os[r * 68 + cc] / lrow[r];
        attout[(size_t)(b * SEQ + qb + r) * DMODEL + h * DK + cc] = __float2half(v);
    }
}

// ---------------- fused residual + LayerNorm ----------------
__device__ __forceinline__ float block_sum256(float v, float* red) {
#pragma unroll
    for (int o = 16; o; o >>= 1) v += __shfl_xor_sync(0xffffffffu, v, o);
    int tid = threadIdx.x;
    if ((tid & 31) == 0) red[tid >> 5] = v;
    __syncthreads();
    float s = 0.0f;
#pragma unroll
    for (int w = 0; w < 8; w++) s += red[w];
    __syncthreads();
    return s;
}

__global__ void __launch_bounds__(256) ln_kernel(
    const float* __restrict__ a, const float* __restrict__ b,
    const float* __restrict__ g, const float* __restrict__ be,
    float* __restrict__ out, __half* __restrict__ outh)
{
    __shared__ float red[8];
    const int row = blockIdx.x, tid = threadIdx.x;
    const size_t base = (size_t)row * DMODEL;
    float v[4];
    float s = 0.0f;
#pragma unroll
    for (int i = 0; i < 4; i++) {
        int c = tid + 256 * i;
        v[i] = a[base + c] + b[base + c];
        s += v[i];
    }
    float mu = block_sum256(s, red) * (1.0f / DMODEL);
    float q = 0.0f;
#pragma unroll
    for (int i = 0; i < 4; i++) { float d = v[i] - mu; q += d * d; }
    float var = block_sum256(q, red) * (1.0f / DMODEL);
    float rstd = rsqrtf(var + LN_EPS);
#pragma unroll
    for (int i = 0; i < 4; i++) {
        int c = tid + 256 * i;
        float o = (v[i] - mu) * rstd * g[c] + be[c];
        out[base + c] = o;
        if (outh) outh[base + c] = __float2half(o);
    }
}

// ---------------- host launcher ----------------
static void* sym(const void* s) { void* p = nullptr; cudaGetSymbolAddress(&p, s); return p; }

extern "C" void kernel_launch(void* const* d_in, const int* in_sizes, int n_in,
                              void* d_out, int out_size)
{
    const float* x   = (const float*)d_in[0];
    const float* wts = (const float*)d_in[1];
    const float* Wq  = (const float*)d_in[2];
    const float* bq  = (const float*)d_in[3];
    const float* Wk  = (const float*)d_in[4];
    const float* bk  = (const float*)d_in[5];
    const float* Wv  = (const float*)d_in[6];
    const float* bv  = (const float*)d_in[7];
    const float* Wo  = (const float*)d_in[8];
    const float* bo  = (const float*)d_in[9];
    const float* W1  = (const float*)d_in[10];
    const float* b1  = (const float*)d_in[11];
    const float* W2  = (const float*)d_in[12];
    const float* b2  = (const float*)d_in[13];
    const float* g1  = (const float*)d_in[14];
    const float* be1 = (const float*)d_in[15];
    const float* g2  = (const float*)d_in[16];
    const float* be2 = (const float*)d_in[17];

    __half* xb   = (__half*)sym(g_xb);
    __half* Wqb  = (__half*)sym(g_Wqb);
    __half* Wkb  = (__half*)sym(g_Wkb);
    __half* Wvb  = (__half*)sym(g_Wvb);
    __half* Wob  = (__half*)sym(g_Wob);
    __half* W1b  = (__half*)sym(g_W1b);
    __half* W2b  = (__half*)sym(g_W2b);
    __half* Qd   = (__half*)sym(g_Q);
    __half* Kd   = (__half*)sym(g_K);
    __half* Vd   = (__half*)sym(g_V);
    __half* attb = (__half*)sym(g_att);
    float*  oproj= (float*)sym(g_oproj);
    float*  hbuf = (float*)sym(g_h);
    __half* hb   = (__half*)sym(g_hb);
    __half* y1   = (__half*)sym(g_y1);
    float*  ffn2 = (float*)sym(g_ffn2);
    float*  logw = (float*)sym(g_logw);

    cudaFuncSetAttribute((const void*)flash_attn,
                         cudaFuncAttributeMaxDynamicSharedMemorySize, FLASH_SMEM);

    const int T = 256;
    // fp32 -> fp16 conversions
    f2h_kernel<<<(NTOK*DMODEL + T-1)/T, T>>>(x,  xb,  NTOK*DMODEL);
    f2h_kernel<<<(DMODEL*DMODEL + T-1)/T, T>>>(Wq, Wqb, DMODEL*DMODEL);
    f2h_kernel<<<(DMODEL*DMODEL + T-1)/T, T>>>(Wk, Wkb, DMODEL*DMODEL);
    f2h_kernel<<<(DMODEL*DMODEL + T-1)/T, T>>>(Wv, Wvb, DMODEL*DMODEL);
    f2h_kernel<<<(DMODEL*DMODEL + T-1)/T, T>>>(Wo, Wob, DMODEL*DMODEL);
    f2h_kernel<<<(DMODEL*DFF + T-1)/T, T>>>(W1, W1b, DMODEL*DFF);
    f2h_kernel<<<(DFF*DMODEL + T-1)/T, T>>>(W2, W2b, DFF*DMODEL);
    logw_kernel<<<(NTOK + T-1)/T, T>>>(wts, logw, NTOK);

    // Q, K, V projections (scattered to [B,H,S,DK])
    dim3 gQKV(DMODEL/BN, NTOK/BM);
    gemm_f16<3><<<gQKV, 256>>>(xb, Wqb, bq, Qd, NTOK, DMODEL, DMODEL);
    gemm_f16<3><<<gQKV, 256>>>(xb, Wkb, bk, Kd, NTOK, DMODEL, DMODEL);
    gemm_f16<3><<<gQKV, 256>>>(xb, Wvb, bv, Vd, NTOK, DMODEL, DMODEL);

    // attention
    flash_attn<<<dim3(SEQ/64, BATCH*NHEADS), 128, FLASH_SMEM>>>(Qd, Kd, Vd, logw, attb);

    // output projection (fp32)
    gemm_f16<0><<<dim3(DMODEL/BN, NTOK/BM), 256>>>(attb, Wob, bo, oproj,
                                                   NTOK, DMODEL, DMODEL);
    // h = LN(x + attn_out), also fp16 copy
    ln_kernel<<<NTOK, 256>>>(x, oproj, g1, be1, hbuf, hb);

    // FFN
    gemm_f16<2><<<dim3(DFF/BN, NTOK/BM), 256>>>(hb, W1b, b1, y1, NTOK, DFF, DMODEL);
    gemm_f16<0><<<dim3(DMODEL/BN, NTOK/BM), 256>>>(y1, W2b, b2, ffn2, NTOK, DMODEL, DFF);

    // out = LN(h + ffn)
    ln_kernel<<<NTOK, 256>>>(hbuf, ffn2, g2, be2, (float*)d_out, nullptr);
}

// round 17
// speedup vs baseline: 1.0090x; 1.0012x over previous
#include <cuda_runtime.h>
#include <cuda_fp16.h>
#include <mma.h>

using namespace nvcuda;

// ---------------- problem constants ----------------
#define DMODEL 1024
#define NHEADS 16
#define DK     64
#define DFF    4096
#define BATCH  2
#define SEQ    2048
#define NTOK   (BATCH*SEQ)          // 4096
#define LN_EPS 1e-3f

// ---------------- scratch (device globals; no allocation allowed) -------------
__device__ __half g_xb   [NTOK*DMODEL];
__device__ __half g_Wqb  [DMODEL*DMODEL];
__device__ __half g_Wkb  [DMODEL*DMODEL];
__device__ __half g_Wvb  [DMODEL*DMODEL];
__device__ __half g_Wob  [DMODEL*DMODEL];
__device__ __half g_W1b  [DMODEL*DFF];
__device__ __half g_W2b  [DFF*DMODEL];
__device__ __half g_Q    [NTOK*DMODEL];   // [B,H,S,DK]
__device__ __half g_K    [NTOK*DMODEL];   // [B,H,S,DK]
__device__ __half g_V    [NTOK*DMODEL];   // [B,H,S,DK]
__device__ __half g_att  [NTOK*DMODEL];   // [tok, DMODEL]
__device__ float  g_oproj[NTOK*DMODEL];
__device__ float  g_h    [NTOK*DMODEL];
__device__ __half g_hb   [NTOK*DMODEL];
__device__ __half g_y1   [NTOK*DFF];
__device__ float  g_ffn2 [NTOK*DMODEL];
__device__ float  g_logw [NTOK];

// ---------------- tiny elementwise kernels ----------------
__global__ void f2h_kernel(const float* __restrict__ a, __half* __restrict__ o, int n) {
    int i = blockIdx.x * blockDim.x + threadIdx.x;
    if (i < n) o[i] = __float2half(a[i]);
}

__global__ void logw_kernel(const float* __restrict__ w, float* __restrict__ o, int n) {
    int i = blockIdx.x * blockDim.x + threadIdx.x;
    if (i < n) o[i] = logf(w[i] + 1e-20f);
}

// ---------------- generic fp16 GEMM with fused epilogue ----------------
// C = A(MxK) @ B(KxN) + bias, fp32 accumulate.
// EPI: 0 -> fp32 row-major; 1 -> fp16 row-major; 2 -> relu + fp16 row-major;
//      3 -> fp16 scattered to [B,H,S,DK] layout (QKV)
#define BM 128
#define BN 128
#define BKK 32

template<int EPI>
__global__ void __launch_bounds__(256) gemm_f16(
    const __half* __restrict__ A, const __half* __restrict__ B,
    const float* __restrict__ bias, void* __restrict__ C,
    int M, int N, int K)
{
    __shared__ __half As[BM][BKK + 8];   // ld 40 (80B, mult of 16B)
    __shared__ __half Bs[BKK][BN + 8];   // ld 136 (272B)
    __shared__ float  epi[8][256];

    const int tid  = threadIdx.x;
    const int bm   = blockIdx.y, bn = blockIdx.x;
    const int warp = tid >> 5, lane = tid & 31;
    const int wr   = warp >> 2, wc = warp & 3;   // 2x4 warp grid; warp tile 64x32

    wmma::fragment<wmma::accumulator, 16, 16, 16, float> c[4][2];
#pragma unroll
    for (int i = 0; i < 4; i++)
#pragma unroll
        for (int j = 0; j < 2; j++) wmma::fill_fragment(c[i][j], 0.0f);

    const __half* Ab = A + (size_t)bm * BM * K;
    const __half* Bb = B + (size_t)bn * BN;

    const int arow = tid >> 2, acol = (tid & 3) * 8;
    const int brow = tid >> 4, bcol = (tid & 15) * 8;

    for (int k0 = 0; k0 < K; k0 += BKK) {
#pragma unroll
        for (int i = 0; i < 2; i++) {
            int r = arow + i * 64;
            *(int4*)&As[r][acol] = *(const int4*)&Ab[(size_t)r * K + k0 + acol];
        }
#pragma unroll
        for (int i = 0; i < 2; i++) {
            int r = brow + i * 16;
            *(int4*)&Bs[r][bcol] = *(const int4*)&Bb[(size_t)(k0 + r) * N + bcol];
        }
        __syncthreads();

#pragma unroll
        for (int kk = 0; kk < BKK; kk += 16) {
            wmma::fragment<wmma::matrix_a, 16, 16, 16, __half, wmma::row_major> a[4];
            wmma::fragment<wmma::matrix_b, 16, 16, 16, __half, wmma::row_major> b[2];
#pragma unroll
            for (int i = 0; i < 4; i++)
                wmma::load_matrix_sync(a[i], &As[wr * 64 + i * 16][kk], BKK + 8);
#pragma unroll
            for (int j = 0; j < 2; j++)
                wmma::load_matrix_sync(b[j], &Bs[kk][wc * 32 + j * 16], BN + 8);
#pragma unroll
            for (int i = 0; i < 4; i++)
#pragma unroll
                for (int j = 0; j < 2; j++)
                    wmma::mma_sync(c[i][j], a[i], b[j], c[i][j]);
        }
        __syncthreads();
    }

    // epilogue: stage each 16x16 frag through smem, apply bias + EPI, store
#pragma unroll
    for (int i = 0; i < 4; i++) {
#pragma unroll
        for (int j = 0; j < 2; j++) {
            wmma::store_matrix_sync(epi[warp], c[i][j], 16, wmma::mem_row_major);
            __syncwarp();
            const int gr0 = bm * BM + wr * 64 + i * 16;
            const int gc0 = bn * BN + wc * 32 + j * 16;
#pragma unroll
            for (int e = 0; e < 8; e++) {
                int idx = lane * 8 + e;
                int r = idx >> 4, cc = idx & 15;
                int grow = gr0 + r, gcol = gc0 + cc;
                float v = epi[warp][idx] + bias[gcol];
                if (EPI == 0) {
                    ((float*)C)[(size_t)grow * N + gcol] = v;
                } else if (EPI == 1) {
                    ((__half*)C)[(size_t)grow * N + gcol] = __float2half(v);
                } else if (EPI == 2) {
                    ((__half*)C)[(size_t)grow * N + gcol] = __float2half(fmaxf(v, 0.0f));
                } else { // QKV scatter: grow = token, gcol = channel
                    int b_ = grow >> 11, s_ = grow & 2047;
                    int h_ = gcol >> 6,  d_ = gcol & 63;
                    ((__half*)C)[((((size_t)b_ * NHEADS + h_) * SEQ + s_) << 6) + d_] =
                        __float2half(v);
                }
            }
            __syncwarp();
        }
    }
}

// ---------------- flash attention ----------------
// grid: (SEQ/64, BATCH*NHEADS), 128 threads (4 warps). Br=Bc=64, D=64.
// Q pre-scaled by 1/sqrt(DK). Scores get per-key log-weight bias.
#define FLASH_SMEM (4*64*72*2 /*Qs,Ks,Vs,Ps*/ + 2*64*68*4 /*Ss,Os*/ + 4*64*4)

__global__ void __launch_bounds__(128) flash_attn(
    const __half* __restrict__ Q, const __half* __restrict__ K,
    const __half* __restrict__ V, const float* __restrict__ logw,
    __half* __restrict__ attout)
{
    extern __shared__ char smem[];
    __half* Qs = (__half*)smem;           // 64 x 72
    __half* Ks = Qs + 64 * 72;
    __half* Vs = Ks + 64 * 72;
    __half* Ps = Vs + 64 * 72;
    float*  Ss = (float*)(Ps + 64 * 72);  // 64 x 68
    float*  Os = Ss + 64 * 68;            // 64 x 68
    float*  lw   = Os + 64 * 68;          // 64
    float*  mrow = lw + 64;
    float*  lrow = mrow + 64;
    float*  arow = lrow + 64;

    const int tid = threadIdx.x;
    const int warp = tid >> 5;
    const int qb = blockIdx.x * 64;
    const int bh = blockIdx.y;            // b*16 + h
    const int b  = bh >> 4;
    const int h  = bh & 15;

    const __half* Qbase = Q + ((size_t)bh * SEQ + qb) * DK;
    const __half* Kb    = K + (size_t)bh * SEQ * DK;
    const __half* Vb    = V + (size_t)bh * SEQ * DK;
    const float*  lwb   = logw + b * SEQ;

    // load Q tile, scaled by 1/8
    for (int i = tid; i < 64 * 8; i += 128) {
        int r = i >> 3, c8 = (i & 7) * 8;
        int4 v4 = *(const int4*)&Qbase[r * DK + c8];
        __half* hv = (__half*)&v4;
#pragma unroll
        for (int e = 0; e < 8; e++) hv[e] = __float2half(__half2float(hv[e]) * 0.125f);
        *(int4*)&Qs[r * 72 + c8] = v4;
    }
    for (int i = tid; i < 64 * 68; i += 128) Os[i] = 0.0f;
    if (tid < 64) { mrow[tid] = -1e30f; lrow[tid] = 0.0f; }
    __syncthreads();

    for (int kt = 0; kt < SEQ; kt += 64) {
        // load K/V tiles + log-weight slice
        for (int i = tid; i < 512; i += 128) {
            int r = i >> 3, c8 = (i & 7) * 8;
            *(int4*)&Ks[r * 72 + c8] = *(const int4*)&Kb[(size_t)(kt + r) * DK + c8];
            *(int4*)&Vs[r * 72 + c8] = *(const int4*)&Vb[(size_t)(kt + r) * DK + c8];
        }
        if (tid < 64) lw[tid] = lwb[kt + tid];
        __syncthreads();

        // S = Q @ K^T  (warp owns 16 rows)
        {
            wmma::fragment<wmma::accumulator, 16, 16, 16, float> s[4];
#pragma unroll
            for (int n = 0; n < 4; n++) wmma::fill_fragment(s[n], 0.0f);
#pragma unroll
            for (int k = 0; k < 4; k++) {
                wmma::fragment<wmma::matrix_a, 16, 16, 16, __half, wmma::row_major> a;
                wmma::load_matrix_sync(a, &Qs[(warp * 16) * 72 + k * 16], 72);
#pragma unroll
                for (int n = 0; n < 4; n++) {
                    wmma::fragment<wmma::matrix_b, 16, 16, 16, __half, wmma::col_major> bb;
                    wmma::load_matrix_sync(bb, &Ks[(n * 16) * 72 + k * 16], 72);
                    wmma::mma_sync(s[n], a, bb, s[n]);
                }
            }
#pragma unroll
            for (int n = 0; n < 4; n++)
                wmma::store_matrix_sync(&Ss[(warp * 16) * 68 + n * 16], s[n], 68,
                                        wmma::mem_row_major);
        }
        __syncthreads();

        // online softmax: 2 threads per row
        {
            int r = tid >> 1, j = tid & 1;
            float* Sr = &Ss[r * 68 + j * 32];
            const float* lwp = &lw[j * 32];
            float mx = -1e30f;
#pragma unroll
            for (int cc = 0; cc < 32; cc++) {
                float v = Sr[cc] + lwp[cc];
                Sr[cc] = v;
                mx = fmaxf(mx, v);
            }
            mx = fmaxf(mx, __shfl_xor_sync(0xffffffffu, mx, 1));
            float mold = mrow[r];
            float mnew = fmaxf(mold, mx);
            float sum = 0.0f;
            __half* Pr = &Ps[r * 72 + j * 32];
#pragma unroll
            for (int cc = 0; cc < 32; cc++) {
                float p = __expf(Sr[cc] - mnew);
                sum += p;
                Pr[cc] = __float2half(p);
            }
            sum += __shfl_xor_sync(0xffffffffu, sum, 1);
            if (j == 0) {
                float a = __expf(mold - mnew);
                mrow[r] = mnew;
                lrow[r] = lrow[r] * a + sum;
                arow[r] = a;
            }
        }
        __syncthreads();

        // PV = P @ V  -> staged into Ss
        {
            wmma::fragment<wmma::accumulator, 16, 16, 16, float> pv[4];
#pragma unroll
            for (int n = 0; n < 4; n++) wmma::fill_fragment(pv[n], 0.0f);
#pragma unroll
            for (int k = 0; k < 4; k++) {
                wmma::fragment<wmma::matrix_a, 16, 16, 16, __half, wmma::row_major> a;
                wmma::load_matrix_sync(a, &Ps[(warp * 16) * 72 + k * 16], 72);
#pragma unroll
                for (int n = 0; n < 4; n++) {
                    wmma::fragment<wmma::matrix_b, 16, 16, 16, __half, wmma::row_major> bb;
                    wmma::load_matrix_sync(bb, &Vs[(k * 16) * 72 + n * 16], 72);
                    wmma::mma_sync(pv[n], a, bb, pv[n]);
                }
            }
#pragma unroll
            for (int n = 0; n < 4; n++)
                wmma::store_matrix_sync(&Ss[(warp * 16) * 68 + n * 16], pv[n], 68,
                                        wmma::mem_row_major);
        }
        __syncthreads();

        // O = O * alpha + PV
        for (int i = tid; i < 4096; i += 128) {
            int r = i >> 6, cc = i & 63;
            Os[r * 68 + cc] = Os[r * 68 + cc] * arow[r] + Ss[r * 68 + cc];
        }
        __syncthreads();
    }

    // write O / l  to [tok, DMODEL] fp16
    for (int i = tid; i < 4096; i += 128) {
        int r = i >> 6, cc = i & 63;
        float v = Os[r * 68 + cc] / lrow[r];
        attout[(size_t)(b * SEQ + qb + r) * DMODEL + h * DK + cc] = __float2half(v);
    }
}

// ---------------- fused residual + LayerNorm ----------------
__device__ __forceinline__ float block_sum256(float v, float* red) {
#pragma unroll
    for (int o = 16; o; o >>= 1) v += __shfl_xor_sync(0xffffffffu, v, o);
    int tid = threadIdx.x;
    if ((tid & 31) == 0) red[tid >> 5] = v;
    __syncthreads();
    float s = 0.0f;
#pragma unroll
    for (int w = 0; w < 8; w++) s += red[w];
    __syncthreads();
    return s;
}

__global__ void __launch_bounds__(256) ln_kernel(
    const float* __restrict__ a, const float* __restrict__ b,
    const float* __restrict__ g, const float* __restrict__ be,
    float* __restrict__ out, __half* __restrict__ outh)
{
    __shared__ float red[8];
    const int row = blockIdx.x, tid = threadIdx.x;
    const size_t base = (size_t)row * DMODEL;
    float v[4];
    float s = 0.0f;
#pragma unroll
    for (int i = 0; i < 4; i++) {
        int c = tid + 256 * i;
        v[i] = a[base + c] + b[base + c];
        s += v[i];
    }
    float mu = block_sum256(s, red) * (1.0f / DMODEL);
    float q = 0.0f;
#pragma unroll
    for (int i = 0; i < 4; i++) { float d = v[i] - mu; q += d * d; }
    float var = block_sum256(q, red) * (1.0f / DMODEL);
    float rstd = rsqrtf(var + LN_EPS);
#pragma unroll
    for (int i = 0; i < 4; i++) {
        int c = tid + 256 * i;
        float o = (v[i] - mu) * rstd * g[c] + be[c];
        out[base + c] = o;
        if (outh) outh[base + c] = __float2half(o);
    }
}

// ---------------- host launcher ----------------
static void* sym(const void* s) { void* p = nullptr; cudaGetSymbolAddress(&p, s); return p; }

extern "C" void kernel_launch(void* const* d_in, const int* in_sizes, int n_in,
                              void* d_out, int out_size)
{
    const float* x   = (const float*)d_in[0];
    const float* wts = (const float*)d_in[1];
    const float* Wq  = (const float*)d_in[2];
    const float* bq  = (const float*)d_in[3];
    const float* Wk  = (const float*)d_in[4];
    const float* bk  = (const float*)d_in[5];
    const float* Wv  = (const float*)d_in[6];
    const float* bv  = (const float*)d_in[7];
    const float* Wo  = (const float*)d_in[8];
    const float* bo  = (const float*)d_in[9];
    const float* W1  = (const float*)d_in[10];
    const float* b1  = (const float*)d_in[11];
    const float* W2  = (const float*)d_in[12];
    const float* b2  = (const float*)d_in[13];
    const float* g1  = (const float*)d_in[14];
    const float* be1 = (const float*)d_in[15];
    const float* g2  = (const float*)d_in[16];
    const float* be2 = (const float*)d_in[17];

    __half* xb   = (__half*)sym(g_xb);
    __half* Wqb  = (__half*)sym(g_Wqb);
    __half* Wkb  = (__half*)sym(g_Wkb);
    __half* Wvb  = (__half*)sym(g_Wvb);
    __half* Wob  = (__half*)sym(g_Wob);
    __half* W1b  = (__half*)sym(g_W1b);
    __half* W2b  = (__half*)sym(g_W2b);
    __half* Qd   = (__half*)sym(g_Q);
    __half* Kd   = (__half*)sym(g_K);
    __half* Vd   = (__half*)sym(g_V);
    __half* attb = (__half*)sym(g_att);
    float*  oproj= (float*)sym(g_oproj);
    float*  hbuf = (float*)sym(g_h);
    __half* hb   = (__half*)sym(g_hb);
    __half* y1   = (__half*)sym(g_y1);
    float*  ffn2 = (float*)sym(g_ffn2);
    float*  logw = (float*)sym(g_logw);

    cudaFuncSetAttribute((const void*)flash_attn,
                         cudaFuncAttributeMaxDynamicSharedMemorySize, FLASH_SMEM);

    const int T = 256;
    // fp32 -> fp16 conversions
    f2h_kernel<<<(NTOK*DMODEL + T-1)/T, T>>>(x,  xb,  NTOK*DMODEL);
    f2h_kernel<<<(DMODEL*DMODEL + T-1)/T, T>>>(Wq, Wqb, DMODEL*DMODEL);
    f2h_kernel<<<(DMODEL*DMODEL + T-1)/T, T>>>(Wk, Wkb, DMODEL*DMODEL);
    f2h_kernel<<<(DMODEL*DMODEL + T-1)/T, T>>>(Wv, Wvb, DMODEL*DMODEL);
    f2h_kernel<<<(DMODEL*DMODEL + T-1)/T, T>>>(Wo, Wob, DMODEL*DMODEL);
    f2h_kernel<<<(DMODEL*DFF + T-1)/T, T>>>(W1, W1b, DMODEL*DFF);
    f2h_kernel<<<(DFF*DMODEL + T-1)/T, T>>>(W2, W2b, DFF*DMODEL);
    logw_kernel<<<(NTOK + T-1)/T, T>>>(wts, logw, NTOK);

    // Q, K, V projections (scattered to [B,H,S,DK])
    dim3 gQKV(DMODEL/BN, NTOK/BM);
    gemm_f16<3><<<gQKV, 256>>>(xb, Wqb, bq, Qd, NTOK, DMODEL, DMODEL);
    gemm_f16<3><<<gQKV, 256>>>(xb, Wkb, bk, Kd, NTOK, DMODEL, DMODEL);
    gemm_f16<3><<<gQKV, 256>>>(xb, Wvb, bv, Vd, NTOK, DMODEL, DMODEL);

    // attention
    flash_attn<<<dim3(SEQ/64, BATCH*NHEADS), 128, FLASH_SMEM>>>(Qd, Kd, Vd, logw, attb);

    // output projection (fp32)
    gemm_f16<0><<<dim3(DMODEL/BN, NTOK/BM), 256>>>(attb, Wob, bo, oproj,
                                                   NTOK, DMODEL, DMODEL);
    // h = LN(x + attn_out), also fp16 copy
    ln_kernel<<<NTOK, 256>>>(x, oproj, g1, be1, hbuf, hb);

    // FFN
    gemm_f16<2><<<dim3(DFF/BN, NTOK/BM), 256>>>(hb, W1b, b1, y1, NTOK, DFF, DMODEL);
    gemm_f16<0><<<dim3(DMODEL/BN, NTOK/BM), 256>>>(y1, W2b, b2, ffn2, NTOK, DMODEL, DFF);

    // out = LN(h + ffn)
    ln_kernel<<<NTOK, 256>>>(hbuf, ffn2, g2, be2, (float*)d_out, nullptr);
}